// round 1
// baseline (speedup 1.0000x reference)
#include <cuda_runtime.h>

// Problem constants
#define B_    32
#define CIN   192
#define T_    256
#define V_    21
#define H_    3
#define COUT  192
#define OUTD  (H_*COUT)   // 576
#define NTHREADS 192

// Transposed weight: Wt[c][o] = W[o][c], kept in device global (no allocs allowed)
__device__ float g_Wt[CIN * OUTD];

__global__ void transposeW_kernel(const float* __restrict__ W) {
    int idx = blockIdx.x * blockDim.x + threadIdx.x;
    if (idx < OUTD * CIN) {
        int o = idx / CIN;
        int c = idx % CIN;
        g_Wt[c * OUTD + o] = W[idx];
    }
}

extern __shared__ float smem[];

__global__ __launch_bounds__(NTHREADS, 2) void gat_fused_kernel(
    const float* __restrict__ x,      // (B, CIN, T, V)
    const float* __restrict__ A,      // (H, V, V)
    const float* __restrict__ ssrc,   // (1, H, COUT)
    const float* __restrict__ stgt,   // (1, H, COUT)
    float* __restrict__ out)          // (B*T*V, COUT) flat
{
    // Shared memory layout
    float* xs   = smem;               // [CIN][V]  : c*21+v      (4032)
    float* proj = xs + CIN * V_;      // [V][OUTD] : v*576+o     (12096)
    float* ss_s = proj + V_ * OUTD;   // [63] index v*3+h
    float* st_s = ss_s + 63;          // [63]
    float* w_s  = st_s + 63;          // [63][21] attention weights

    const int bp  = blockIdx.x;       // bp = b*T + t
    const int b   = bp >> 8;          // T_ == 256
    const int t   = bp & 255;
    const int tid = threadIdx.x;

    const float* xbase = x + (long)b * CIN * T_ * V_ + (long)t * V_;

    // ---- Phase 1: load x slice (CIN x V) ----
    for (int idx = tid; idx < CIN * V_; idx += NTHREADS) {
        int c = idx / V_;
        int v = idx % V_;
        xs[idx] = xbase[(long)c * (T_ * V_) + v];
    }
    __syncthreads();

    // ---- Phase 2: projection GEMM: proj[v][o] = sum_c xs[c][v] * Wt[c][o] ----
    {
        const int ty = tid / 64;      // 0..2 -> v group of 7
        const int tx = tid % 64;      // o = tx + 64*j
        const int v0 = ty * 7;

        float acc[7][9];
        #pragma unroll
        for (int i = 0; i < 7; i++)
            #pragma unroll
            for (int j = 0; j < 9; j++)
                acc[i][j] = 0.0f;

        for (int c = 0; c < CIN; c++) {
            float wv[9];
            #pragma unroll
            for (int j = 0; j < 9; j++)
                wv[j] = g_Wt[c * OUTD + tx + 64 * j];
            float xv[7];
            #pragma unroll
            for (int i = 0; i < 7; i++)
                xv[i] = xs[c * V_ + v0 + i];   // warp-uniform -> smem broadcast
            #pragma unroll
            for (int i = 0; i < 7; i++)
                #pragma unroll
                for (int j = 0; j < 9; j++)
                    acc[i][j] = fmaf(xv[i], wv[j], acc[i][j]);
        }

        #pragma unroll
        for (int i = 0; i < 7; i++)
            #pragma unroll
            for (int j = 0; j < 9; j++)
                proj[(v0 + i) * OUTD + tx + 64 * j] = acc[i][j];
    }
    __syncthreads();

    // ---- Phase 3: attention logits ss/st per (v,h) ----
    {
        const int wid  = tid >> 5;
        const int lane = tid & 31;
        for (int p = wid; p < 63; p += 6) {
            int v = p / 3, h = p % 3;
            const float* pr = proj + v * OUTD + h * COUT;
            const float* s1p = ssrc + h * COUT;
            const float* s2p = stgt + h * COUT;
            float s1 = 0.f, s2 = 0.f;
            for (int c = lane; c < COUT; c += 32) {
                float pv = pr[c];
                s1 = fmaf(pv, s1p[c], s1);
                s2 = fmaf(pv, s2p[c], s2);
            }
            #pragma unroll
            for (int off = 16; off; off >>= 1) {
                s1 += __shfl_down_sync(0xffffffffu, s1, off);
                s2 += __shfl_down_sync(0xffffffffu, s2, off);
            }
            if (lane == 0) { ss_s[p] = s1; st_s[p] = s2; }
        }
    }
    __syncthreads();

    // ---- Phase 4: masked softmax weights, one (h,i) row per thread ----
    if (tid < 63) {
        const int h = tid / 21;
        const int i = tid % 21;
        const float ssi = ss_s[i * 3 + h];
        const float* Arow = A + (h * V_ + i) * V_;
        float sc[21];
        float mx = -1e30f;
        #pragma unroll
        for (int j = 0; j < V_; j++) {
            float a = Arow[j];
            float s = ssi + st_s[j * 3 + h];
            s = (s >= 0.f) ? s : 0.2f * s;   // leaky relu
            s += a;                          // + A_masked (a==1 on valid entries)
            sc[j] = (a != 0.f) ? s : -1e30f;
            mx = fmaxf(mx, sc[j]);
        }
        float sum = 0.f;
        #pragma unroll
        for (int j = 0; j < V_; j++) {
            float e = (sc[j] > -1e29f) ? __expf(sc[j] - mx) : 0.f;
            sc[j] = e;
            sum += e;
        }
        float inv = 1.0f / sum;
        #pragma unroll
        for (int j = 0; j < V_; j++)
            w_s[tid * V_ + j] = sc[j] * inv;
    }
    __syncthreads();

    // ---- Phase 5: aggregation + skip + mean, direct coalesced global write ----
    // result[r][c] = (1/3) * ( sum_{k=0..2} attn_out[h=r/7, i=3*(r%7)+k, c]
    //                        + sum_{head=0..2} proj[r][head*COUT + c] )
    {
        const int c = tid;  // 0..191
        float* op = out + (long)bp * V_ * COUT;
        for (int r = 0; r < V_; r++) {
            int h = r / 7;
            int q = r % 7;
            float acc2 = proj[r * OUTD + c]
                       + proj[r * OUTD + COUT + c]
                       + proj[r * OUTD + 2 * COUT + c];
            const float* pc = proj + h * COUT + c;  // stride OUTD over j
            #pragma unroll
            for (int k = 0; k < 3; k++) {
                int i = 3 * q + k;
                const float* wr = w_s + (h * 21 + i) * V_;
                float a = 0.f;
                #pragma unroll
                for (int j = 0; j < V_; j++)
                    a = fmaf(wr[j], pc[j * OUTD], a);
                acc2 += a;
            }
            op[r * COUT + c] = acc2 * (1.0f / 3.0f);
        }
    }
}

extern "C" void kernel_launch(void* const* d_in, const int* in_sizes, int n_in,
                              void* d_out, int out_size) {
    const float* x    = (const float*)d_in[0];
    const float* A    = (const float*)d_in[1];
    const float* W    = (const float*)d_in[2];
    const float* ssrc = (const float*)d_in[3];
    const float* stgt = (const float*)d_in[4];
    float* out = (float*)d_out;

    // Transpose W into c-major layout for coalesced GEMM reads
    int wtot = OUTD * CIN;
    transposeW_kernel<<<(wtot + 255) / 256, 256>>>(W);

    const int smem_bytes = (CIN * V_ + V_ * OUTD + 63 + 63 + 63 * V_) * (int)sizeof(float);
    static bool attr_set = false;
    if (!attr_set) {
        cudaFuncSetAttribute(gat_fused_kernel,
                             cudaFuncAttributeMaxDynamicSharedMemorySize, smem_bytes);
        attr_set = true;
    }
    gat_fused_kernel<<<B_ * T_, NTHREADS, smem_bytes>>>(x, A, ssrc, stgt, out);
}

// round 4
// speedup vs baseline: 2.1180x; 2.1180x over previous
#include <cuda_runtime.h>
#include <cstdint>

// ---------------- Problem constants ----------------
#define B_    32
#define CIN   192
#define T_    256
#define V_    21
#define H_    3
#define COUT  192
#define OUTD  (H_*COUT)        // 576
#define NROWS (B_*T_*V_)       // 172032
#define PPB   (T_*V_)          // 5376 rows per batch

// ---------------- GEMM tiling ----------------
#define MT    128
#define KD    192
#define NT    72               // N chunk (576 = 8*72)
#define NCHK  8
#define ASTR  136              // A smem row stride in floats
#define BSTR  196              // B smem row stride in floats
#define SMEM_A_BYTES (KD*ASTR*4)        // 104448
#define SMEM_B_BYTES (NT*BSTR*4)        // 56448
#define GEMM_SMEM (SMEM_A_BYTES + 2*SMEM_B_BYTES)  // 217344

// ---------------- Device scratch ----------------
__device__ float    g_proj[(size_t)NROWS * OUTD];   // 396 MB
__device__ uint32_t g_Wt32[OUTD * CIN];             // W pre-converted to tf32 bits

// ---------------- helpers ----------------
__device__ __forceinline__ uint32_t smem_u32(const void* p) {
    uint32_t a;
    asm("{ .reg .u64 t; cvta.to.shared.u64 t, %1; cvt.u32.u64 %0, t; }"
        : "=r"(a) : "l"(p));
    return a;
}
__device__ __forceinline__ void cp_async16(uint32_t dst, const void* src) {
    asm volatile("cp.async.cg.shared.global [%0], [%1], 16;"
                 :: "r"(dst), "l"(src) : "memory");
}
#define CP_COMMIT() asm volatile("cp.async.commit_group;" ::: "memory")
#define CP_WAIT0()  asm volatile("cp.async.wait_group 0;" ::: "memory")

__device__ __forceinline__ uint32_t f2tf32(float f) {
    uint32_t u;
    asm("cvt.rna.tf32.f32 %0, %1;" : "=r"(u) : "f"(f));
    return u;
}

__device__ __forceinline__ void mma_tf32(float& d0, float& d1, float& d2, float& d3,
                                         uint32_t a0, uint32_t a1, uint32_t a2, uint32_t a3,
                                         uint32_t b0, uint32_t b1) {
    asm volatile(
        "mma.sync.aligned.m16n8k8.row.col.f32.tf32.tf32.f32 "
        "{%0,%1,%2,%3}, {%4,%5,%6,%7}, {%8,%9}, {%0,%1,%2,%3};"
        : "+f"(d0), "+f"(d1), "+f"(d2), "+f"(d3)
        : "r"(a0), "r"(a1), "r"(a2), "r"(a3), "r"(b0), "r"(b1));
}

// ---------------- Kernel 0: pre-convert W to tf32 bits ----------------
__global__ __launch_bounds__(256) void cvtW_kernel(const float* __restrict__ W) {
    int i = blockIdx.x * blockDim.x + threadIdx.x;
    if (i < OUTD * CIN) g_Wt32[i] = f2tf32(W[i]);
}

// ---------------- Kernel 1: tf32 mma.sync GEMM: proj = X @ W^T ----------------
__global__ __launch_bounds__(256, 1) void gemm_kernel(const float* __restrict__ x) {
    extern __shared__ char smem[];
    float*    smA = (float*)smem;                                   // [KD][ASTR]
    uint32_t* smB = (uint32_t*)(smem + SMEM_A_BYTES);               // 2 x [NT][BSTR]
    const uint32_t sA = smem_u32(smA);
    const uint32_t sB = smem_u32(smB);

    const int tid  = threadIdx.x;
    const int warp = tid >> 5;
    const int lane = tid & 31;
    const int g    = lane >> 2;      // groupID 0..7
    const int kq   = lane & 3;       // threadID_in_group 0..3
    const int mw   = warp * 16;      // warp's M offset in tile

    const size_t m0   = (size_t)blockIdx.x * MT;
    const int    b    = (int)(m0 / PPB);
    const int    poff = (int)(m0 % PPB);
    const float* xb   = x + (size_t)b * CIN * PPB + poff;

    // ---- A tile: 192 channels x 128 floats (contiguous runs in x) ----
    for (int i = tid; i < KD * 32; i += 256) {
        int c = i >> 5, seg = i & 31;
        cp_async16(sA + c * (ASTR * 4) + seg * 16, xb + (size_t)c * PPB + seg * 4);
    }
    // ---- B chunk 0: 72 rows x 192 tf32 values = 48 x 16B segments per row ----
    for (int i = tid; i < NT * 48; i += 256) {
        int r = i / 48, seg = i % 48;
        cp_async16(sB + r * (BSTR * 4) + seg * 16, g_Wt32 + (size_t)r * CIN + seg * 4);
    }
    CP_COMMIT();
    CP_WAIT0();
    __syncthreads();

    for (int ch = 0; ch < NCHK; ch++) {
        // prefetch next B chunk into other buffer
        if (ch + 1 < NCHK) {
            uint32_t dstb = sB + ((ch + 1) & 1) * SMEM_B_BYTES;
            const uint32_t* src = g_Wt32 + (size_t)(ch + 1) * NT * CIN;
            for (int i = tid; i < NT * 48; i += 256) {
                int r = i / 48, seg = i % 48;
                cp_async16(dstb + r * (BSTR * 4) + seg * 16, src + (size_t)r * CIN + seg * 4);
            }
            CP_COMMIT();
        }

        const uint32_t* Bc = smB + (ch & 1) * (SMEM_B_BYTES / 4);
        float acc[9][4];
        #pragma unroll
        for (int f = 0; f < 9; f++)
            #pragma unroll
            for (int q = 0; q < 4; q++) acc[f][q] = 0.0f;

        #pragma unroll 4
        for (int kk = 0; kk < KD / 8; kk++) {
            const int k0 = kk * 8;
            uint32_t a0 = f2tf32(smA[(k0 + kq) * ASTR + mw + g]);
            uint32_t a1 = f2tf32(smA[(k0 + kq) * ASTR + mw + g + 8]);
            uint32_t a2 = f2tf32(smA[(k0 + kq + 4) * ASTR + mw + g]);
            uint32_t a3 = f2tf32(smA[(k0 + kq + 4) * ASTR + mw + g + 8]);
            #pragma unroll
            for (int f = 0; f < 9; f++) {
                uint32_t b0 = Bc[(f * 8 + g) * BSTR + k0 + kq];
                uint32_t b1 = Bc[(f * 8 + g) * BSTR + k0 + kq + 4];
                mma_tf32(acc[f][0], acc[f][1], acc[f][2], acc[f][3],
                         a0, a1, a2, a3, b0, b1);
            }
        }

        // ---- epilogue: write this chunk's columns straight to g_proj ----
        {
            const int n0 = ch * NT;
            float* r0p = g_proj + (m0 + mw + g) * OUTD + n0 + 2 * kq;
            float* r1p = r0p + 8 * OUTD;
            #pragma unroll
            for (int f = 0; f < 9; f++) {
                *(float2*)(r0p + f * 8) = make_float2(acc[f][0], acc[f][1]);
                *(float2*)(r1p + f * 8) = make_float2(acc[f][2], acc[f][3]);
            }
        }

        if (ch + 1 < NCHK) CP_WAIT0();
        __syncthreads();
    }
}

// ---------------- Kernel 2: attention + aggregation + skip/mean ----------------
#define NTHREADS 192
extern __shared__ float asmem[];

__global__ __launch_bounds__(NTHREADS) void gat_attn_kernel(
    const float* __restrict__ A,      // (H, V, V)
    const float* __restrict__ ssrc,   // (1, H, COUT)
    const float* __restrict__ stgt,   // (1, H, COUT)
    float* __restrict__ out)          // (NROWS, COUT) flat
{
    float* proj = asmem;              // [V][OUTD] 12096
    float* ss_s = proj + V_ * OUTD;   // [63] index v*3+h
    float* st_s = ss_s + 63;          // [63]
    float* w_s  = st_s + 63;          // [63][21]

    const int bp  = blockIdx.x;
    const int tid = threadIdx.x;

    // Phase 1: load proj tile (21 x 576) from global
    {
        const float4* src = (const float4*)(g_proj + (size_t)bp * V_ * OUTD);
        float4* dst = (float4*)proj;
        for (int i = tid; i < V_ * OUTD / 4; i += NTHREADS)
            dst[i] = src[i];
    }
    __syncthreads();

    // Phase 2: attention logits ss/st per (v,h)
    {
        const int wid  = tid >> 5;
        const int lane = tid & 31;
        for (int p = wid; p < 63; p += 6) {
            int v = p / 3, h = p % 3;
            const float* pr  = proj + v * OUTD + h * COUT;
            const float* s1p = ssrc + h * COUT;
            const float* s2p = stgt + h * COUT;
            float s1 = 0.f, s2 = 0.f;
            for (int c = lane; c < COUT; c += 32) {
                float pv = pr[c];
                s1 = fmaf(pv, s1p[c], s1);
                s2 = fmaf(pv, s2p[c], s2);
            }
            #pragma unroll
            for (int off = 16; off; off >>= 1) {
                s1 += __shfl_down_sync(0xffffffffu, s1, off);
                s2 += __shfl_down_sync(0xffffffffu, s2, off);
            }
            if (lane == 0) { ss_s[p] = s1; st_s[p] = s2; }
        }
    }
    __syncthreads();

    // Phase 3: masked softmax, one (h,i) row per thread
    if (tid < 63) {
        const int h = tid / 21;
        const int i = tid % 21;
        const float ssi = ss_s[i * 3 + h];
        const float* Arow = A + (h * V_ + i) * V_;
        float sc[21];
        float mx = -1e30f;
        #pragma unroll
        for (int j = 0; j < V_; j++) {
            float a = Arow[j];
            float s = ssi + st_s[j * 3 + h];
            s = (s >= 0.f) ? s : 0.2f * s;
            s += a;
            sc[j] = (a != 0.f) ? s : -1e30f;
            mx = fmaxf(mx, sc[j]);
        }
        float sum = 0.f;
        #pragma unroll
        for (int j = 0; j < V_; j++) {
            float e = (sc[j] > -1e29f) ? __expf(sc[j] - mx) : 0.f;
            sc[j] = e;
            sum += e;
        }
        float inv = 1.0f / sum;
        #pragma unroll
        for (int j = 0; j < V_; j++)
            w_s[tid * V_ + j] = sc[j] * inv;
    }
    __syncthreads();

    // Phase 4: aggregation + skip + mean, coalesced global write
    {
        const int c = tid;   // 0..191
        float* op = out + (size_t)bp * V_ * COUT;
        for (int r = 0; r < V_; r++) {
            int h = r / 7;
            int q = r % 7;
            float acc2 = proj[r * OUTD + c]
                       + proj[r * OUTD + COUT + c]
                       + proj[r * OUTD + 2 * COUT + c];
            const float* pc = proj + h * COUT + c;   // stride OUTD over j
            #pragma unroll
            for (int k = 0; k < 3; k++) {
                int i = 3 * q + k;
                const float* wr = w_s + (h * 21 + i) * V_;
                float a = 0.f;
                #pragma unroll
                for (int j = 0; j < V_; j++)
                    a = fmaf(wr[j], pc[j * OUTD], a);
                acc2 += a;
            }
            op[r * COUT + c] = acc2 * (1.0f / 3.0f);
        }
    }
}

// ---------------- Launch ----------------
extern "C" void kernel_launch(void* const* d_in, const int* in_sizes, int n_in,
                              void* d_out, int out_size) {
    const float* x    = (const float*)d_in[0];
    const float* A    = (const float*)d_in[1];
    const float* W    = (const float*)d_in[2];
    const float* ssrc = (const float*)d_in[3];
    const float* stgt = (const float*)d_in[4];
    float* out = (float*)d_out;

    cudaFuncSetAttribute(gemm_kernel,
                         cudaFuncAttributeMaxDynamicSharedMemorySize, GEMM_SMEM);
    const int attn_smem = (V_ * OUTD + 63 + 63 + 63 * V_) * (int)sizeof(float);
    cudaFuncSetAttribute(gat_attn_kernel,
                         cudaFuncAttributeMaxDynamicSharedMemorySize, attn_smem);

    cvtW_kernel<<<(OUTD * CIN + 255) / 256, 256>>>(W);
    gemm_kernel<<<NROWS / MT, 256, GEMM_SMEM>>>(x);
    gat_attn_kernel<<<B_ * T_, NTHREADS, attn_smem>>>(A, ssrc, stgt, out);
}

// round 5
// speedup vs baseline: 2.7293x; 1.2886x over previous
#include <cuda_runtime.h>
#include <cstdint>

// ---------------- Problem constants ----------------
#define B_    32
#define CIN   192
#define T_    256
#define V_    21
#define H_    3
#define COUT  192
#define OUTD  (H_*COUT)        // 576
#define NROWS (B_*T_*V_)       // 172032
#define PPB   (T_*V_)          // 5376 rows per batch

// ---------------- GEMM tiling ----------------
#define MT    128
#define KD    192
#define NT    72               // N chunk (576 = 8*72)
#define NCHK  8
#define ASTR  136              // A smem row stride in floats
#define BSTR  196              // B smem row stride in floats
#define SMEM_A_BYTES (KD*ASTR*4)        // 104448
#define SMEM_B_BYTES (NT*BSTR*4)        // 56448
#define GEMM_SMEM (SMEM_A_BYTES + 2*SMEM_B_BYTES)  // 217344

// ---------------- Device scratch ----------------
__device__ float    g_proj[(size_t)NROWS * OUTD];   // 396 MB
__device__ uint32_t g_Wt32[OUTD * CIN];             // W pre-converted to tf32 bits

// ---------------- helpers ----------------
__device__ __forceinline__ uint32_t smem_u32(const void* p) {
    uint32_t a;
    asm("{ .reg .u64 t; cvta.to.shared.u64 t, %1; cvt.u32.u64 %0, t; }"
        : "=r"(a) : "l"(p));
    return a;
}
__device__ __forceinline__ void cp_async16(uint32_t dst, const void* src) {
    asm volatile("cp.async.cg.shared.global [%0], [%1], 16;"
                 :: "r"(dst), "l"(src) : "memory");
}
#define CP_COMMIT() asm volatile("cp.async.commit_group;" ::: "memory")
#define CP_WAIT0()  asm volatile("cp.async.wait_group 0;" ::: "memory")

__device__ __forceinline__ uint32_t f2tf32(float f) {
    uint32_t u;
    asm("cvt.rna.tf32.f32 %0, %1;" : "=r"(u) : "f"(f));
    return u;
}

__device__ __forceinline__ void mma_tf32(float* d,
                                         uint32_t a0, uint32_t a1, uint32_t a2, uint32_t a3,
                                         uint32_t b0, uint32_t b1) {
    asm volatile(
        "mma.sync.aligned.m16n8k8.row.col.f32.tf32.tf32.f32 "
        "{%0,%1,%2,%3}, {%4,%5,%6,%7}, {%8,%9}, {%0,%1,%2,%3};"
        : "+f"(d[0]), "+f"(d[1]), "+f"(d[2]), "+f"(d[3])
        : "r"(a0), "r"(a1), "r"(a2), "r"(a3), "r"(b0), "r"(b1));
}

// ---------------- Kernel 0: pre-convert W to tf32 bits ----------------
__global__ __launch_bounds__(256) void cvtW_kernel(const float* __restrict__ W) {
    int i = blockIdx.x * blockDim.x + threadIdx.x;
    if (i < OUTD * CIN) g_Wt32[i] = f2tf32(W[i]);
}

// ---------------- Kernel 1: tf32 mma.sync GEMM: proj = X @ W^T ----------------
// 128 threads, 4 warps, each warp owns M32 (2 x m16 frags), all 72 N cols.
__global__ __launch_bounds__(128, 1) void gemm_kernel(const float* __restrict__ x) {
    extern __shared__ char smem[];
    float*    smA = (float*)smem;                                   // [KD][ASTR]
    uint32_t* smB = (uint32_t*)(smem + SMEM_A_BYTES);               // 2 x [NT][BSTR]
    const uint32_t sA = smem_u32(smA);
    const uint32_t sB = smem_u32(smB);

    const int tid  = threadIdx.x;
    const int warp = tid >> 5;
    const int lane = tid & 31;
    const int g    = lane >> 2;      // groupID 0..7
    const int kq   = lane & 3;       // threadID_in_group 0..3
    const int mw   = warp * 32;      // warp's M offset in tile

    const size_t m0   = (size_t)blockIdx.x * MT;
    const int    b    = (int)(m0 / PPB);
    const int    poff = (int)(m0 % PPB);
    const float* xb   = x + (size_t)b * CIN * PPB + poff;

    // ---- A tile: 192 channels x 128 floats (contiguous runs in x) ----
    for (int i = tid; i < KD * 32; i += 128) {
        int c = i >> 5, seg = i & 31;
        cp_async16(sA + c * (ASTR * 4) + seg * 16, xb + (size_t)c * PPB + seg * 4);
    }
    // ---- B chunk 0: 72 rows x 192 tf32 values = 48 x 16B segments per row ----
    for (int i = tid; i < NT * 48; i += 128) {
        int r = i / 48, seg = i % 48;
        cp_async16(sB + r * (BSTR * 4) + seg * 16, g_Wt32 + (size_t)r * CIN + seg * 4);
    }
    CP_COMMIT();
    CP_WAIT0();
    __syncthreads();

    for (int ch = 0; ch < NCHK; ch++) {
        // prefetch next B chunk into other buffer
        if (ch + 1 < NCHK) {
            uint32_t dstb = sB + ((ch + 1) & 1) * SMEM_B_BYTES;
            const uint32_t* src = g_Wt32 + (size_t)(ch + 1) * NT * CIN;
            for (int i = tid; i < NT * 48; i += 128) {
                int r = i / 48, seg = i % 48;
                cp_async16(dstb + r * (BSTR * 4) + seg * 16, src + (size_t)r * CIN + seg * 4);
            }
            CP_COMMIT();
        }

        const uint32_t* Bc = smB + (ch & 1) * (SMEM_B_BYTES / 4);
        float acc[9][2][4];
        #pragma unroll
        for (int f = 0; f < 9; f++)
            #pragma unroll
            for (int m = 0; m < 2; m++)
                #pragma unroll
                for (int q = 0; q < 4; q++) acc[f][m][q] = 0.0f;

        #pragma unroll 4
        for (int kk = 0; kk < KD / 8; kk++) {
            const int k0 = kk * 8;
            const float* Ak0 = smA + (k0 + kq) * ASTR + mw + g;
            const float* Ak4 = smA + (k0 + kq + 4) * ASTR + mw + g;
            uint32_t a[2][4];
            #pragma unroll
            for (int m = 0; m < 2; m++) {
                a[m][0] = f2tf32(Ak0[m * 16]);
                a[m][1] = f2tf32(Ak0[m * 16 + 8]);
                a[m][2] = f2tf32(Ak4[m * 16]);
                a[m][3] = f2tf32(Ak4[m * 16 + 8]);
            }
            #pragma unroll
            for (int f = 0; f < 9; f++) {
                uint32_t b0 = Bc[(f * 8 + g) * BSTR + k0 + kq];
                uint32_t b1 = Bc[(f * 8 + g) * BSTR + k0 + kq + 4];
                mma_tf32(acc[f][0], a[0][0], a[0][1], a[0][2], a[0][3], b0, b1);
                mma_tf32(acc[f][1], a[1][0], a[1][1], a[1][2], a[1][3], b0, b1);
            }
        }

        // ---- epilogue: write this chunk's columns straight to g_proj ----
        {
            const int n0 = ch * NT;
            float* base = g_proj + (m0 + mw + g) * OUTD + n0 + 2 * kq;
            #pragma unroll
            for (int m = 0; m < 2; m++) {
                float* r0p = base + m * 16 * OUTD;
                float* r1p = r0p + 8 * OUTD;
                #pragma unroll
                for (int f = 0; f < 9; f++) {
                    *(float2*)(r0p + f * 8) = make_float2(acc[f][m][0], acc[f][m][1]);
                    *(float2*)(r1p + f * 8) = make_float2(acc[f][m][2], acc[f][m][3]);
                }
            }
        }

        if (ch + 1 < NCHK) CP_WAIT0();
        __syncthreads();
    }
}

// ---------------- Kernel 2: attention + aggregation + skip/mean ----------------
#define NTHREADS 192
extern __shared__ float asmem[];

__global__ __launch_bounds__(NTHREADS) void gat_attn_kernel(
    const float* __restrict__ A,      // (H, V, V)
    const float* __restrict__ ssrc,   // (1, H, COUT)
    const float* __restrict__ stgt,   // (1, H, COUT)
    float* __restrict__ out)          // (NROWS, COUT) flat
{
    float* proj = asmem;              // [V][OUTD] 12096
    float* ss_s = proj + V_ * OUTD;   // [63] index v*3+h
    float* st_s = ss_s + 63;          // [63]
    float* w_s  = st_s + 63;          // [63][21]
    float* wsum = w_s + 63 * V_;      // [21][21]: row r = h*7+q

    const int bp  = blockIdx.x;
    const int tid = threadIdx.x;

    // Phase 1: load proj tile (21 x 576) from global
    {
        const float4* src = (const float4*)(g_proj + (size_t)bp * V_ * OUTD);
        float4* dst = (float4*)proj;
        for (int i = tid; i < V_ * OUTD / 4; i += NTHREADS)
            dst[i] = src[i];
    }
    __syncthreads();

    // Phase 2: attention logits ss/st per (v,h)
    {
        const int wid  = tid >> 5;
        const int lane = tid & 31;
        for (int p = wid; p < 63; p += 6) {
            int v = p / 3, h = p % 3;
            const float* pr  = proj + v * OUTD + h * COUT;
            const float* s1p = ssrc + h * COUT;
            const float* s2p = stgt + h * COUT;
            float s1 = 0.f, s2 = 0.f;
            for (int c = lane; c < COUT; c += 32) {
                float pv = pr[c];
                s1 = fmaf(pv, s1p[c], s1);
                s2 = fmaf(pv, s2p[c], s2);
            }
            #pragma unroll
            for (int off = 16; off; off >>= 1) {
                s1 += __shfl_down_sync(0xffffffffu, s1, off);
                s2 += __shfl_down_sync(0xffffffffu, s2, off);
            }
            if (lane == 0) { ss_s[p] = s1; st_s[p] = s2; }
        }
    }
    __syncthreads();

    // Phase 3: masked softmax, one (h,i) row per thread
    if (tid < 63) {
        const int h = tid / 21;
        const int i = tid % 21;
        const float ssi = ss_s[i * 3 + h];
        const float* Arow = A + (h * V_ + i) * V_;
        float sc[21];
        float mx = -1e30f;
        #pragma unroll
        for (int j = 0; j < V_; j++) {
            float a = Arow[j];
            float s = ssi + st_s[j * 3 + h];
            s = (s >= 0.f) ? s : 0.2f * s;
            s += a;
            sc[j] = (a != 0.f) ? s : -1e30f;
            mx = fmaxf(mx, sc[j]);
        }
        float sum = 0.f;
        #pragma unroll
        for (int j = 0; j < V_; j++) {
            float e = (sc[j] > -1e29f) ? __expf(sc[j] - mx) : 0.f;
            sc[j] = e;
            sum += e;
        }
        float inv = 1.0f / sum;
        #pragma unroll
        for (int j = 0; j < V_; j++)
            w_s[tid * V_ + j] = sc[j] * inv;
    }
    __syncthreads();

    // Phase 3.5: pre-sum the 3 attention rows feeding each output row.
    // Output row r (= h*7+q) consumes attention rows i = 3q..3q+2 of head h.
    for (int idx = tid; idx < V_ * V_; idx += NTHREADS) {
        int r = idx / V_, j = idx % V_;
        int h = r / 7, q = r % 7;
        int i0 = h * 21 + 3 * q;
        wsum[idx] = w_s[(i0 + 0) * V_ + j]
                  + w_s[(i0 + 1) * V_ + j]
                  + w_s[(i0 + 2) * V_ + j];
    }
    __syncthreads();

    // Phase 4: aggregation + skip + mean, proj column hoisted per head
    {
        const int c = tid;   // 0..191
        float* op = out + (size_t)bp * V_ * COUT;
        #pragma unroll
        for (int h = 0; h < H_; h++) {
            float p[21];
            #pragma unroll
            for (int j = 0; j < V_; j++)
                p[j] = proj[j * OUTD + h * COUT + c];
            #pragma unroll
            for (int q = 0; q < 7; q++) {
                const int r = h * 7 + q;
                const float* ws = wsum + r * V_;
                float acc = proj[r * OUTD + c]
                          + proj[r * OUTD + COUT + c]
                          + proj[r * OUTD + 2 * COUT + c];
                #pragma unroll
                for (int j = 0; j < V_; j++)
                    acc = fmaf(ws[j], p[j], acc);
                op[r * COUT + c] = acc * (1.0f / 3.0f);
            }
        }
    }
}

// ---------------- Launch ----------------
extern "C" void kernel_launch(void* const* d_in, const int* in_sizes, int n_in,
                              void* d_out, int out_size) {
    const float* x    = (const float*)d_in[0];
    const float* A    = (const float*)d_in[1];
    const float* W    = (const float*)d_in[2];
    const float* ssrc = (const float*)d_in[3];
    const float* stgt = (const float*)d_in[4];
    float* out = (float*)d_out;

    cudaFuncSetAttribute(gemm_kernel,
                         cudaFuncAttributeMaxDynamicSharedMemorySize, GEMM_SMEM);
    const int attn_smem = (V_ * OUTD + 63 + 63 + 63 * V_ + V_ * V_) * (int)sizeof(float);
    cudaFuncSetAttribute(gat_attn_kernel,
                         cudaFuncAttributeMaxDynamicSharedMemorySize, attn_smem);

    cvtW_kernel<<<(OUTD * CIN + 255) / 256, 256>>>(W);
    gemm_kernel<<<NROWS / MT, 128, GEMM_SMEM>>>(x);
    gat_attn_kernel<<<B_ * T_, NTHREADS, attn_smem>>>(A, ssrc, stgt, out);
}

// round 9
// speedup vs baseline: 3.3431x; 1.2249x over previous
#include <cuda_runtime.h>
#include <cuda_fp16.h>
#include <cstdint>

// ---------------- Problem constants ----------------
#define B_    32
#define CIN   192
#define T_    256
#define V_    21
#define H_    3
#define COUT  192
#define OUTD  (H_*COUT)        // 576
#define NROWS (B_*T_*V_)       // 172032
#define PPB   (T_*V_)          // 5376

// ---------------- GEMM tiling ----------------
#define MT    128              // M tile (1344 blocks)
#define NTC   32               // N chunk (576 = 18*32)
#define NCH   18
#define AST   200              // A smem row stride (halves)
#define BST   200              // B smem row stride (halves)
#define SMEM_A_BYTES (MT*AST*2)          // 51200
#define SMEM_B_BYTES (NTC*BST*2)         // 12800
#define GEMM_SMEM (SMEM_A_BYTES + 2*SMEM_B_BYTES)  // 76800

// ---------------- Device scratch ----------------
__device__ float  g_proj[(size_t)NROWS * OUTD];   // 396 MB
__device__ __half g_Xh[(size_t)NROWS * CIN];      // 66 MB: x transposed+fp16
__device__ __half g_Wh[OUTD * CIN];               // W fp16

// ---------------- helpers ----------------
__device__ __forceinline__ uint32_t smem_u32(const void* p) {
    uint32_t a;
    asm("{ .reg .u64 t; cvta.to.shared.u64 t, %1; cvt.u32.u64 %0, t; }"
        : "=r"(a) : "l"(p));
    return a;
}
__device__ __forceinline__ void cp_async16(uint32_t dst, const void* src) {
    asm volatile("cp.async.cg.shared.global [%0], [%1], 16;"
                 :: "r"(dst), "l"(src) : "memory");
}
#define CP_COMMIT() asm volatile("cp.async.commit_group;" ::: "memory")
#define CP_WAIT0()  asm volatile("cp.async.wait_group 0;" ::: "memory")

__device__ __forceinline__ void ldmat_x4(uint32_t* r, uint32_t addr) {
    asm volatile("ldmatrix.sync.aligned.m8n8.x4.shared.b16 {%0,%1,%2,%3}, [%4];"
                 : "=r"(r[0]), "=r"(r[1]), "=r"(r[2]), "=r"(r[3]) : "r"(addr));
}
__device__ __forceinline__ void mma_f16(float* d, const uint32_t* a,
                                        uint32_t b0, uint32_t b1) {
    asm volatile(
        "mma.sync.aligned.m16n8k16.row.col.f32.f16.f16.f32 "
        "{%0,%1,%2,%3}, {%4,%5,%6,%7}, {%8,%9}, {%0,%1,%2,%3};"
        : "+f"(d[0]), "+f"(d[1]), "+f"(d[2]), "+f"(d[3])
        : "r"(a[0]), "r"(a[1]), "r"(a[2]), "r"(a[3]), "r"(b0), "r"(b1));
}

// ---------------- Kernel 0a: transpose+convert x -> g_Xh[(b,p)][c] fp16 ----------------
__global__ __launch_bounds__(256) void cvtX_kernel(const float* __restrict__ x) {
    __shared__ float tile[32][33];
    const int b  = blockIdx.z;
    const int c0 = blockIdx.y * 32;
    const int p0 = blockIdx.x * 32;
    const int tx = threadIdx.x;     // 32
    const int ty = threadIdx.y;     // 8
    const float* xb = x + (size_t)b * CIN * PPB;
    #pragma unroll
    for (int k = 0; k < 4; k++)
        tile[ty + k * 8][tx] = xb[(size_t)(c0 + ty + k * 8) * PPB + p0 + tx];
    __syncthreads();
    __half* xo = g_Xh + ((size_t)b * PPB + p0) * CIN + c0;
    #pragma unroll
    for (int k = 0; k < 4; k++)
        xo[(size_t)(ty + k * 8) * CIN + tx] = __float2half_rn(tile[tx][ty + k * 8]);
}

// ---------------- Kernel 0b: convert W -> fp16 ----------------
__global__ __launch_bounds__(256) void cvtW_kernel(const float* __restrict__ W) {
    int i = blockIdx.x * blockDim.x + threadIdx.x;
    if (i < OUTD * CIN) g_Wh[i] = __float2half_rn(W[i]);
}

// ---------------- Kernel 1: fp16 mma GEMM: proj = Xh @ Wh^T (fp32 accum) ----------------
__global__ __launch_bounds__(128, 2) void gemm_kernel() {
    extern __shared__ char smem[];
    const uint32_t sA = smem_u32(smem);
    const uint32_t sB = sA + SMEM_A_BYTES;

    const int tid  = threadIdx.x;
    const int warp = tid >> 5;
    const int lane = tid & 31;
    const int g    = lane >> 2;
    const int kq   = lane & 3;

    const size_t m0 = (size_t)blockIdx.x * MT;

    // ---- A tile: 128 rows x 192 halves = 24 x 16B segs per row ----
    for (int i = tid; i < MT * 24; i += 128) {
        int r = i / 24, s = i % 24;
        cp_async16(sA + r * (AST * 2) + s * 16, g_Xh + (m0 + r) * CIN + s * 8);
    }
    // ---- B chunk 0: 32 rows x 24 segs ----
    for (int i = tid; i < NTC * 24; i += 128) {
        int r = i / 24, s = i % 24;
        cp_async16(sB + r * (BST * 2) + s * 16, g_Wh + (size_t)r * CIN + s * 8);
    }
    CP_COMMIT();
    CP_WAIT0();
    __syncthreads();

    // A (non-trans): lanes 0-7 rows0-7@k0, 8-15 rows8-15@k0, 16-23 rows0-7@k8, 24-31 rows8-15@k8
    const int aRow = warp * 32 + (lane & 15);
    const uint32_t aBase = sA + aRow * (AST * 2) + ((lane >> 4) * 8) * 2;
    // B (non-trans on [n][k] rows): lanes 0-7 n0-7@k0, 8-15 n0-7@k8, 16-23 n8-15@k0, 24-31 n8-15@k8
    const int bN   = (lane & 7) + ((lane >> 4) << 3);
    const uint32_t bKof = (((lane >> 3) & 1) * 8) * 2;

    for (int ch = 0; ch < NCH; ch++) {
        if (ch + 1 < NCH) {
            uint32_t dstb = sB + ((ch + 1) & 1) * SMEM_B_BYTES;
            const __half* src = g_Wh + (size_t)(ch + 1) * NTC * CIN;
            for (int i = tid; i < NTC * 24; i += 128) {
                int r = i / 24, s = i % 24;
                cp_async16(dstb + r * (BST * 2) + s * 16, src + (size_t)r * CIN + s * 8);
            }
            CP_COMMIT();
        }

        const uint32_t sBc = sB + (ch & 1) * SMEM_B_BYTES;
        const uint32_t bBase0 = sBc + bN * (BST * 2) + bKof;       // n 0..15
        const uint32_t bBase1 = bBase0 + 16 * (BST * 2);           // n 16..31

        float acc[4][2][4];
        #pragma unroll
        for (int f = 0; f < 4; f++)
            #pragma unroll
            for (int m = 0; m < 2; m++)
                #pragma unroll
                for (int q = 0; q < 4; q++) acc[f][m][q] = 0.0f;

        #pragma unroll 4
        for (int kk = 0; kk < 12; kk++) {
            const uint32_t kof = kk * 32;   // 16 halves
            uint32_t a[2][4], br[2][4];
            ldmat_x4(a[0], aBase + kof);
            ldmat_x4(a[1], aBase + 16 * (AST * 2) + kof);
            ldmat_x4(br[0], bBase0 + kof);
            ldmat_x4(br[1], bBase1 + kof);
            #pragma unroll
            for (int i2 = 0; i2 < 2; i2++)
                #pragma unroll
                for (int t = 0; t < 2; t++) {
                    const int f = i2 * 2 + t;
                    // br[i2]: reg0=(n+0..7,k0-7) reg1=(n+0..7,k8-15)
                    //         reg2=(n+8..15,k0-7) reg3=(n+8..15,k8-15)
                    mma_f16(acc[f][0], a[0], br[i2][t * 2], br[i2][t * 2 + 1]);
                    mma_f16(acc[f][1], a[1], br[i2][t * 2], br[i2][t * 2 + 1]);
                }
        }

        // ---- epilogue: write chunk's 32 columns to g_proj ----
        {
            const int n0c = ch * NTC;
            #pragma unroll
            for (int m = 0; m < 2; m++) {
                float* r0p = g_proj + (m0 + warp * 32 + m * 16 + g) * OUTD + n0c + 2 * kq;
                float* r1p = r0p + 8 * OUTD;
                #pragma unroll
                for (int f = 0; f < 4; f++) {
                    const int nOf = (f >> 1) * 16 + (f & 1) * 8;  // i2*16 + t*8
                    *(float2*)(r0p + nOf) = make_float2(acc[f][m][0], acc[f][m][1]);
                    *(float2*)(r1p + nOf) = make_float2(acc[f][m][2], acc[f][m][3]);
                }
            }
        }

        if (ch + 1 < NCH) CP_WAIT0();
        __syncthreads();
    }
}

// ---------------- Kernel 2: attention + aggregation + skip/mean ----------------
#define NTHREADS 192
extern __shared__ float asmem[];

__global__ __launch_bounds__(NTHREADS) void gat_attn_kernel(
    const float* __restrict__ A,      // (H, V, V)
    const float* __restrict__ ssrc,   // (1, H, COUT)
    const float* __restrict__ stgt,   // (1, H, COUT)
    float* __restrict__ out)          // (NROWS, COUT) flat
{
    float* proj = asmem;              // [V][OUTD]
    float* ss_s = proj + V_ * OUTD;   // [63]
    float* st_s = ss_s + 63;          // [63]
    float* w_s  = st_s + 63;          // [63][21]
    float* wsum = w_s + 63 * V_;      // [21][21]

    const int bp  = blockIdx.x;
    const int tid = threadIdx.x;

    {
        const float4* src = (const float4*)(g_proj + (size_t)bp * V_ * OUTD);
        float4* dst = (float4*)proj;
        for (int i = tid; i < V_ * OUTD / 4; i += NTHREADS)
            dst[i] = src[i];
    }
    __syncthreads();

    {
        const int wid  = tid >> 5;
        const int lane = tid & 31;
        for (int p = wid; p < 63; p += 6) {
            int v = p / 3, h = p % 3;
            const float* pr  = proj + v * OUTD + h * COUT;
            const float* s1p = ssrc + h * COUT;
            const float* s2p = stgt + h * COUT;
            float s1 = 0.f, s2 = 0.f;
            for (int c = lane; c < COUT; c += 32) {
                float pv = pr[c];
                s1 = fmaf(pv, s1p[c], s1);
                s2 = fmaf(pv, s2p[c], s2);
            }
            #pragma unroll
            for (int off = 16; off; off >>= 1) {
                s1 += __shfl_down_sync(0xffffffffu, s1, off);
                s2 += __shfl_down_sync(0xffffffffu, s2, off);
            }
            if (lane == 0) { ss_s[p] = s1; st_s[p] = s2; }
        }
    }
    __syncthreads();

    if (tid < 63) {
        const int h = tid / 21;
        const int i = tid % 21;
        const float ssi = ss_s[i * 3 + h];
        const float* Arow = A + (h * V_ + i) * V_;
        float sc[21];
        float mx = -1e30f;
        #pragma unroll
        for (int j = 0; j < V_; j++) {
            float a = Arow[j];
            float s = ssi + st_s[j * 3 + h];
            s = (s >= 0.f) ? s : 0.2f * s;
            s += a;
            sc[j] = (a != 0.f) ? s : -1e30f;
            mx = fmaxf(mx, sc[j]);
        }
        float sum = 0.f;
        #pragma unroll
        for (int j = 0; j < V_; j++) {
            float e = (sc[j] > -1e29f) ? __expf(sc[j] - mx) : 0.f;
            sc[j] = e;
            sum += e;
        }
        float inv = 1.0f / sum;
        #pragma unroll
        for (int j = 0; j < V_; j++)
            w_s[tid * V_ + j] = sc[j] * inv;
    }
    __syncthreads();

    for (int idx = tid; idx < V_ * V_; idx += NTHREADS) {
        int r = idx / V_, j = idx % V_;
        int h = r / 7, q = r % 7;
        int i0 = h * 21 + 3 * q;
        wsum[idx] = w_s[(i0 + 0) * V_ + j]
                  + w_s[(i0 + 1) * V_ + j]
                  + w_s[(i0 + 2) * V_ + j];
    }
    __syncthreads();

    {
        const int c = tid;
        float* op = out + (size_t)bp * V_ * COUT;
        #pragma unroll
        for (int h = 0; h < H_; h++) {
            float p[21];
            #pragma unroll
            for (int j = 0; j < V_; j++)
                p[j] = proj[j * OUTD + h * COUT + c];
            #pragma unroll
            for (int q = 0; q < 7; q++) {
                const int r = h * 7 + q;
                const float* ws = wsum + r * V_;
                float acc = proj[r * OUTD + c]
                          + proj[r * OUTD + COUT + c]
                          + proj[r * OUTD + 2 * COUT + c];
                #pragma unroll
                for (int j = 0; j < V_; j++)
                    acc = fmaf(ws[j], p[j], acc);
                op[r * COUT + c] = acc * (1.0f / 3.0f);
            }
        }
    }
}

// ---------------- Launch ----------------
extern "C" void kernel_launch(void* const* d_in, const int* in_sizes, int n_in,
                              void* d_out, int out_size) {
    const float* x    = (const float*)d_in[0];
    const float* A    = (const float*)d_in[1];
    const float* W    = (const float*)d_in[2];
    const float* ssrc = (const float*)d_in[3];
    const float* stgt = (const float*)d_in[4];
    float* out = (float*)d_out;

    cudaFuncSetAttribute(gemm_kernel,
                         cudaFuncAttributeMaxDynamicSharedMemorySize, GEMM_SMEM);
    const int attn_smem = (V_ * OUTD + 63 + 63 + 63 * V_ + V_ * V_) * (int)sizeof(float);
    cudaFuncSetAttribute(gat_attn_kernel,
                         cudaFuncAttributeMaxDynamicSharedMemorySize, attn_smem);

    cvtX_kernel<<<dim3(PPB / 32, CIN / 32, B_), dim3(32, 8)>>>(x);
    cvtW_kernel<<<(OUTD * CIN + 255) / 256, 256>>>(W);
    gemm_kernel<<<NROWS / MT, 128, GEMM_SMEM>>>();
    gat_attn_kernel<<<B_ * T_, NTHREADS, attn_smem>>>(A, ssrc, stgt, out);
}

// round 10
// speedup vs baseline: 3.7970x; 1.1358x over previous
#include <cuda_runtime.h>
#include <cuda_fp16.h>
#include <cstdint>

// ---------------- Problem constants ----------------
#define B_    32
#define CIN   192
#define T_    256
#define V_    21
#define H_    3
#define COUT  192
#define OUTD  (H_*COUT)        // 576
#define NROWS (B_*T_*V_)       // 172032
#define PPB   (T_*V_)          // 5376

// ---------------- GEMM tiling ----------------
#define MT    128              // M tile (1344 blocks)
#define NTC   32               // N chunk (576 = 18*32)
#define NCH   18
#define AST   200              // A smem row stride (halves)
#define BST   200              // B smem row stride (halves)
#define SMEM_A_BYTES (MT*AST*2)          // 51200
#define SMEM_B_BYTES (NTC*BST*2)         // 12800
#define GEMM_SMEM (SMEM_A_BYTES + 2*SMEM_B_BYTES)  // 76800

// ---------------- Device scratch ----------------
__device__ __half g_projh[(size_t)NROWS * OUTD];  // 198 MB (fp16 intermediate)
__device__ __half g_Xh[(size_t)NROWS * CIN];      // 66 MB: x transposed+fp16
__device__ __half g_Wh[OUTD * CIN];               // W fp16

// ---------------- helpers ----------------
__device__ __forceinline__ uint32_t smem_u32(const void* p) {
    uint32_t a;
    asm("{ .reg .u64 t; cvta.to.shared.u64 t, %1; cvt.u32.u64 %0, t; }"
        : "=r"(a) : "l"(p));
    return a;
}
__device__ __forceinline__ void cp_async16(uint32_t dst, const void* src) {
    asm volatile("cp.async.cg.shared.global [%0], [%1], 16;"
                 :: "r"(dst), "l"(src) : "memory");
}
#define CP_COMMIT() asm volatile("cp.async.commit_group;" ::: "memory")
#define CP_WAIT0()  asm volatile("cp.async.wait_group 0;" ::: "memory")

__device__ __forceinline__ void ldmat_x4(uint32_t* r, uint32_t addr) {
    asm volatile("ldmatrix.sync.aligned.m8n8.x4.shared.b16 {%0,%1,%2,%3}, [%4];"
                 : "=r"(r[0]), "=r"(r[1]), "=r"(r[2]), "=r"(r[3]) : "r"(addr));
}
__device__ __forceinline__ void mma_f16(float* d, const uint32_t* a,
                                        uint32_t b0, uint32_t b1) {
    asm volatile(
        "mma.sync.aligned.m16n8k16.row.col.f32.f16.f16.f32 "
        "{%0,%1,%2,%3}, {%4,%5,%6,%7}, {%8,%9}, {%0,%1,%2,%3};"
        : "+f"(d[0]), "+f"(d[1]), "+f"(d[2]), "+f"(d[3])
        : "r"(a[0]), "r"(a[1]), "r"(a[2]), "r"(a[3]), "r"(b0), "r"(b1));
}

// ---------------- Kernel 0a: transpose+convert x -> g_Xh[(b,p)][c] fp16 ----------------
__global__ __launch_bounds__(256) void cvtX_kernel(const float* __restrict__ x) {
    __shared__ float tile[32][33];
    const int b  = blockIdx.z;
    const int c0 = blockIdx.y * 32;
    const int p0 = blockIdx.x * 32;
    const int tx = threadIdx.x;     // 32
    const int ty = threadIdx.y;     // 8
    const float* xb = x + (size_t)b * CIN * PPB;
    #pragma unroll
    for (int k = 0; k < 4; k++)
        tile[ty + k * 8][tx] = xb[(size_t)(c0 + ty + k * 8) * PPB + p0 + tx];
    __syncthreads();
    __half* xo = g_Xh + ((size_t)b * PPB + p0) * CIN + c0;
    #pragma unroll
    for (int k = 0; k < 4; k++)
        xo[(size_t)(ty + k * 8) * CIN + tx] = __float2half_rn(tile[tx][ty + k * 8]);
}

// ---------------- Kernel 0b: convert W -> fp16 ----------------
__global__ __launch_bounds__(256) void cvtW_kernel(const float* __restrict__ W) {
    int i = blockIdx.x * blockDim.x + threadIdx.x;
    if (i < OUTD * CIN) g_Wh[i] = __float2half_rn(W[i]);
}

// ---------------- Kernel 1: fp16 mma GEMM: projh = Xh @ Wh^T (fp32 accum) ----------------
__global__ __launch_bounds__(128, 2) void gemm_kernel() {
    extern __shared__ char smem[];
    const uint32_t sA = smem_u32(smem);
    const uint32_t sB = sA + SMEM_A_BYTES;

    const int tid  = threadIdx.x;
    const int warp = tid >> 5;
    const int lane = tid & 31;
    const int g    = lane >> 2;
    const int kq   = lane & 3;

    const size_t m0 = (size_t)blockIdx.x * MT;

    // ---- A tile: 128 rows x 192 halves = 24 x 16B segs per row ----
    for (int i = tid; i < MT * 24; i += 128) {
        int r = i / 24, s = i % 24;
        cp_async16(sA + r * (AST * 2) + s * 16, g_Xh + (m0 + r) * CIN + s * 8);
    }
    // ---- B chunk 0: 32 rows x 24 segs ----
    for (int i = tid; i < NTC * 24; i += 128) {
        int r = i / 24, s = i % 24;
        cp_async16(sB + r * (BST * 2) + s * 16, g_Wh + (size_t)r * CIN + s * 8);
    }
    CP_COMMIT();
    CP_WAIT0();
    __syncthreads();

    const int aRow = warp * 32 + (lane & 15);
    const uint32_t aBase = sA + aRow * (AST * 2) + ((lane >> 4) * 8) * 2;
    const int bN   = (lane & 7) + ((lane >> 4) << 3);
    const uint32_t bKof = (((lane >> 3) & 1) * 8) * 2;

    for (int ch = 0; ch < NCH; ch++) {
        if (ch + 1 < NCH) {
            uint32_t dstb = sB + ((ch + 1) & 1) * SMEM_B_BYTES;
            const __half* src = g_Wh + (size_t)(ch + 1) * NTC * CIN;
            for (int i = tid; i < NTC * 24; i += 128) {
                int r = i / 24, s = i % 24;
                cp_async16(dstb + r * (BST * 2) + s * 16, src + (size_t)r * CIN + s * 8);
            }
            CP_COMMIT();
        }

        const uint32_t sBc = sB + (ch & 1) * SMEM_B_BYTES;
        const uint32_t bBase0 = sBc + bN * (BST * 2) + bKof;       // n 0..15
        const uint32_t bBase1 = bBase0 + 16 * (BST * 2);           // n 16..31

        float acc[4][2][4];
        #pragma unroll
        for (int f = 0; f < 4; f++)
            #pragma unroll
            for (int m = 0; m < 2; m++)
                #pragma unroll
                for (int q = 0; q < 4; q++) acc[f][m][q] = 0.0f;

        #pragma unroll 4
        for (int kk = 0; kk < 12; kk++) {
            const uint32_t kof = kk * 32;   // 16 halves
            uint32_t a[2][4], br[2][4];
            ldmat_x4(a[0], aBase + kof);
            ldmat_x4(a[1], aBase + 16 * (AST * 2) + kof);
            ldmat_x4(br[0], bBase0 + kof);
            ldmat_x4(br[1], bBase1 + kof);
            #pragma unroll
            for (int i2 = 0; i2 < 2; i2++)
                #pragma unroll
                for (int t = 0; t < 2; t++) {
                    const int f = i2 * 2 + t;
                    mma_f16(acc[f][0], a[0], br[i2][t * 2], br[i2][t * 2 + 1]);
                    mma_f16(acc[f][1], a[1], br[i2][t * 2], br[i2][t * 2 + 1]);
                }
        }

        // ---- epilogue: write chunk's 32 columns as fp16 ----
        {
            const int n0c = ch * NTC;
            #pragma unroll
            for (int m = 0; m < 2; m++) {
                __half* r0p = g_projh + (m0 + warp * 32 + m * 16 + g) * OUTD + n0c + 2 * kq;
                __half* r1p = r0p + 8 * OUTD;
                #pragma unroll
                for (int f = 0; f < 4; f++) {
                    const int nOf = (f >> 1) * 16 + (f & 1) * 8;  // i2*16 + t*8
                    *(__half2*)(r0p + nOf) = __floats2half2_rn(acc[f][m][0], acc[f][m][1]);
                    *(__half2*)(r1p + nOf) = __floats2half2_rn(acc[f][m][2], acc[f][m][3]);
                }
            }
        }

        if (ch + 1 < NCH) CP_WAIT0();
        __syncthreads();
    }
}

// ---------------- Kernel 2: attention + aggregation + skip/mean ----------------
#define NTHREADS 192
extern __shared__ char asmem_raw[];

__global__ __launch_bounds__(NTHREADS) void gat_attn_kernel(
    const float* __restrict__ A,      // (H, V, V)
    const float* __restrict__ ssrc,   // (1, H, COUT)
    const float* __restrict__ stgt,   // (1, H, COUT)
    float* __restrict__ out)          // (NROWS, COUT) flat
{
    __half* projh = (__half*)asmem_raw;                 // [V][OUTD] halves, 24192 B
    float*  fbase = (float*)(asmem_raw + ((V_ * OUTD * 2 + 15) & ~15));
    float* ss_s = fbase;              // [63]
    float* st_s = ss_s + 63;          // [63]
    float* w_s  = st_s + 63;          // [63][21]
    float* wsum = w_s + 63 * V_;      // [21][21]

    const int bp  = blockIdx.x;
    const int tid = threadIdx.x;

    // Phase 1: load proj tile (21 x 576 halves = 1512 uint4)
    {
        const uint4* src = (const uint4*)(g_projh + (size_t)bp * V_ * OUTD);
        uint4* dst = (uint4*)projh;
        for (int i = tid; i < V_ * OUTD * 2 / 16; i += NTHREADS)
            dst[i] = src[i];
    }
    __syncthreads();

    // Phase 2: attention logits ss/st per (v,h)
    {
        const int wid  = tid >> 5;
        const int lane = tid & 31;
        for (int p = wid; p < 63; p += 6) {
            int v = p / 3, h = p % 3;
            const __half2* pr2 = (const __half2*)(projh + v * OUTD + h * COUT);
            const float* s1p = ssrc + h * COUT;
            const float* s2p = stgt + h * COUT;
            float s1 = 0.f, s2 = 0.f;
            for (int c2 = lane; c2 < COUT / 2; c2 += 32) {
                float2 pv = __half22float2(pr2[c2]);
                s1 = fmaf(pv.x, s1p[2 * c2], fmaf(pv.y, s1p[2 * c2 + 1], s1));
                s2 = fmaf(pv.x, s2p[2 * c2], fmaf(pv.y, s2p[2 * c2 + 1], s2));
            }
            #pragma unroll
            for (int off = 16; off; off >>= 1) {
                s1 += __shfl_down_sync(0xffffffffu, s1, off);
                s2 += __shfl_down_sync(0xffffffffu, s2, off);
            }
            if (lane == 0) { ss_s[p] = s1; st_s[p] = s2; }
        }
    }
    __syncthreads();

    // Phase 3: masked softmax, one (h,i) row per thread
    if (tid < 63) {
        const int h = tid / 21;
        const int i = tid % 21;
        const float ssi = ss_s[i * 3 + h];
        const float* Arow = A + (h * V_ + i) * V_;
        float sc[21];
        float mx = -1e30f;
        #pragma unroll
        for (int j = 0; j < V_; j++) {
            float a = Arow[j];
            float s = ssi + st_s[j * 3 + h];
            s = (s >= 0.f) ? s : 0.2f * s;
            s += a;
            sc[j] = (a != 0.f) ? s : -1e30f;
            mx = fmaxf(mx, sc[j]);
        }
        float sum = 0.f;
        #pragma unroll
        for (int j = 0; j < V_; j++) {
            float e = (sc[j] > -1e29f) ? __expf(sc[j] - mx) : 0.f;
            sc[j] = e;
            sum += e;
        }
        float inv = 1.0f / sum;
        #pragma unroll
        for (int j = 0; j < V_; j++)
            w_s[tid * V_ + j] = sc[j] * inv;
    }
    __syncthreads();

    // Phase 3.5: pre-sum the 3 attention rows feeding each output row
    for (int idx = tid; idx < V_ * V_; idx += NTHREADS) {
        int r = idx / V_, j = idx % V_;
        int h = r / 7, q = r % 7;
        int i0 = h * 21 + 3 * q;
        wsum[idx] = w_s[(i0 + 0) * V_ + j]
                  + w_s[(i0 + 1) * V_ + j]
                  + w_s[(i0 + 2) * V_ + j];
    }
    __syncthreads();

    // Phase 4: aggregation + skip + mean
    {
        const int c = tid;
        float* op = out + (size_t)bp * V_ * COUT;
        #pragma unroll
        for (int h = 0; h < H_; h++) {
            float p[21];
            #pragma unroll
            for (int j = 0; j < V_; j++)
                p[j] = __half2float(projh[j * OUTD + h * COUT + c]);
            #pragma unroll
            for (int q = 0; q < 7; q++) {
                const int r = h * 7 + q;
                const float* ws = wsum + r * V_;
                float acc = __half2float(projh[r * OUTD + c])
                          + __half2float(projh[r * OUTD + COUT + c])
                          + __half2float(projh[r * OUTD + 2 * COUT + c]);
                #pragma unroll
                for (int j = 0; j < V_; j++)
                    acc = fmaf(ws[j], p[j], acc);
                op[r * COUT + c] = acc * (1.0f / 3.0f);
            }
        }
    }
}

// ---------------- Launch ----------------
extern "C" void kernel_launch(void* const* d_in, const int* in_sizes, int n_in,
                              void* d_out, int out_size) {
    const float* x    = (const float*)d_in[0];
    const float* A    = (const float*)d_in[1];
    const float* W    = (const float*)d_in[2];
    const float* ssrc = (const float*)d_in[3];
    const float* stgt = (const float*)d_in[4];
    float* out = (float*)d_out;

    cudaFuncSetAttribute(gemm_kernel,
                         cudaFuncAttributeMaxDynamicSharedMemorySize, GEMM_SMEM);
    const int attn_smem = ((V_ * OUTD * 2 + 15) & ~15)
                        + (63 + 63 + 63 * V_ + V_ * V_) * (int)sizeof(float);
    cudaFuncSetAttribute(gat_attn_kernel,
                         cudaFuncAttributeMaxDynamicSharedMemorySize, attn_smem);

    cvtX_kernel<<<dim3(PPB / 32, CIN / 32, B_), dim3(32, 8)>>>(x);
    cvtW_kernel<<<(OUTD * CIN + 255) / 256, 256>>>(W);
    gemm_kernel<<<NROWS / MT, 128, GEMM_SMEM>>>();
    gat_attn_kernel<<<B_ * T_, NTHREADS, attn_smem>>>(A, ssrc, stgt, out);
}

// round 11
// speedup vs baseline: 4.4142x; 1.1625x over previous
#include <cuda_runtime.h>
#include <cuda_fp16.h>
#include <cstdint>

// ---------------- Problem constants ----------------
#define B_    32
#define CIN   192
#define T_    256
#define V_    21
#define H_    3
#define COUT  192
#define OUTD  (H_*COUT)        // 576
#define NROWS (B_*T_*V_)       // 172032
#define PPB   (T_*V_)          // 5376

// ---------------- GEMM tiling ----------------
#define MT    128              // M tile (1344 blocks)
#define NTC   64               // N chunk (576 = 9*64)
#define NCH   9
#define AST   200              // A smem row stride (halves)
#define BST   200              // B smem row stride (halves)
#define SMEM_A_BYTES (MT*AST*2)          // 51200
#define SMEM_B_BYTES (NTC*BST*2)         // 25600
#define GEMM_SMEM (SMEM_A_BYTES + 2*SMEM_B_BYTES)  // 102400

// ---------------- Device scratch ----------------
__device__ __half g_projh[(size_t)NROWS * OUTD];  // 198 MB (fp16 intermediate)
__device__ __half g_Xh[(size_t)NROWS * CIN];      // 66 MB: x transposed+fp16
__device__ __half g_Wh[OUTD * CIN];               // W fp16

// ---------------- helpers ----------------
__device__ __forceinline__ uint32_t smem_u32(const void* p) {
    uint32_t a;
    asm("{ .reg .u64 t; cvta.to.shared.u64 t, %1; cvt.u32.u64 %0, t; }"
        : "=r"(a) : "l"(p));
    return a;
}
__device__ __forceinline__ void cp_async16(uint32_t dst, const void* src) {
    asm volatile("cp.async.cg.shared.global [%0], [%1], 16;"
                 :: "r"(dst), "l"(src) : "memory");
}
#define CP_COMMIT() asm volatile("cp.async.commit_group;" ::: "memory")
#define CP_WAIT0()  asm volatile("cp.async.wait_group 0;" ::: "memory")

__device__ __forceinline__ void ldmat_x4(uint32_t* r, uint32_t addr) {
    asm volatile("ldmatrix.sync.aligned.m8n8.x4.shared.b16 {%0,%1,%2,%3}, [%4];"
                 : "=r"(r[0]), "=r"(r[1]), "=r"(r[2]), "=r"(r[3]) : "r"(addr));
}
__device__ __forceinline__ void mma_f16(float* d, const uint32_t* a,
                                        uint32_t b0, uint32_t b1) {
    asm volatile(
        "mma.sync.aligned.m16n8k16.row.col.f32.f16.f16.f32 "
        "{%0,%1,%2,%3}, {%4,%5,%6,%7}, {%8,%9}, {%0,%1,%2,%3};"
        : "+f"(d[0]), "+f"(d[1]), "+f"(d[2]), "+f"(d[3])
        : "r"(a[0]), "r"(a[1]), "r"(a[2]), "r"(a[3]), "r"(b0), "r"(b1));
}

// ---------------- Kernel 0a: transpose+convert x -> g_Xh[(b,p)][c] fp16 ----------------
__global__ __launch_bounds__(256) void cvtX_kernel(const float* __restrict__ x) {
    __shared__ float tile[32][33];
    const int b  = blockIdx.z;
    const int c0 = blockIdx.y * 32;
    const int p0 = blockIdx.x * 32;
    const int tx = threadIdx.x;     // 32
    const int ty = threadIdx.y;     // 8
    const float* xb = x + (size_t)b * CIN * PPB;
    #pragma unroll
    for (int k = 0; k < 4; k++)
        tile[ty + k * 8][tx] = xb[(size_t)(c0 + ty + k * 8) * PPB + p0 + tx];
    __syncthreads();
    __half* xo = g_Xh + ((size_t)b * PPB + p0) * CIN + c0;
    #pragma unroll
    for (int k = 0; k < 4; k++)
        xo[(size_t)(ty + k * 8) * CIN + tx] = __float2half_rn(tile[tx][ty + k * 8]);
}

// ---------------- Kernel 0b: convert W -> fp16 ----------------
__global__ __launch_bounds__(256) void cvtW_kernel(const float* __restrict__ W) {
    int i = blockIdx.x * blockDim.x + threadIdx.x;
    if (i < OUTD * CIN) g_Wh[i] = __float2half_rn(W[i]);
}

// ---------------- Kernel 1: fp16 mma GEMM: projh = Xh @ Wh^T (fp32 accum) ----------------
__global__ __launch_bounds__(128, 2) void gemm_kernel() {
    extern __shared__ char smem[];
    const uint32_t sA = smem_u32(smem);
    const uint32_t sB = sA + SMEM_A_BYTES;

    const int tid  = threadIdx.x;
    const int warp = tid >> 5;
    const int lane = tid & 31;
    const int g    = lane >> 2;
    const int kq   = lane & 3;

    const size_t m0 = (size_t)blockIdx.x * MT;

    // ---- A tile: 128 rows x 192 halves = 24 x 16B segs per row ----
    for (int i = tid; i < MT * 24; i += 128) {
        int r = i / 24, s = i % 24;
        cp_async16(sA + r * (AST * 2) + s * 16, g_Xh + (m0 + r) * CIN + s * 8);
    }
    // ---- B chunk 0: 64 rows x 24 segs ----
    for (int i = tid; i < NTC * 24; i += 128) {
        int r = i / 24, s = i % 24;
        cp_async16(sB + r * (BST * 2) + s * 16, g_Wh + (size_t)r * CIN + s * 8);
    }
    CP_COMMIT();
    CP_WAIT0();
    __syncthreads();

    // A (non-trans): lanes 0-7 rows0-7@k0, 8-15 rows8-15@k0, 16-23 rows0-7@k8, 24-31 rows8-15@k8
    const int aRow = warp * 32 + (lane & 15);
    const uint32_t aBase = sA + aRow * (AST * 2) + ((lane >> 4) * 8) * 2;
    // B (non-trans on [n][k] rows): lane pattern covers 16 n-rows, 2 k-halves
    const int bN   = (lane & 7) + ((lane >> 4) << 3);
    const uint32_t bKof = (((lane >> 3) & 1) * 8) * 2;

    for (int ch = 0; ch < NCH; ch++) {
        if (ch + 1 < NCH) {
            uint32_t dstb = sB + ((ch + 1) & 1) * SMEM_B_BYTES;
            const __half* src = g_Wh + (size_t)(ch + 1) * NTC * CIN;
            for (int i = tid; i < NTC * 24; i += 128) {
                int r = i / 24, s = i % 24;
                cp_async16(dstb + r * (BST * 2) + s * 16, src + (size_t)r * CIN + s * 8);
            }
            CP_COMMIT();
        }

        const uint32_t sBc = sB + (ch & 1) * SMEM_B_BYTES;
        uint32_t bBase[4];
        #pragma unroll
        for (int i2 = 0; i2 < 4; i2++)
            bBase[i2] = sBc + (i2 * 16 + bN) * (BST * 2) + bKof;

        float acc[8][2][4];
        #pragma unroll
        for (int f = 0; f < 8; f++)
            #pragma unroll
            for (int m = 0; m < 2; m++)
                #pragma unroll
                for (int q = 0; q < 4; q++) acc[f][m][q] = 0.0f;

        #pragma unroll 2
        for (int kk = 0; kk < 12; kk++) {
            const uint32_t kof = kk * 32;   // 16 halves
            uint32_t a[2][4], br[4][4];
            ldmat_x4(a[0], aBase + kof);
            ldmat_x4(a[1], aBase + 16 * (AST * 2) + kof);
            #pragma unroll
            for (int i2 = 0; i2 < 4; i2++)
                ldmat_x4(br[i2], bBase[i2] + kof);
            #pragma unroll
            for (int i2 = 0; i2 < 4; i2++)
                #pragma unroll
                for (int t = 0; t < 2; t++) {
                    const int f = i2 * 2 + t;
                    // br[i2]: reg0=(n+0..7,k0-7) reg1=(n+0..7,k8-15)
                    //         reg2=(n+8..15,k0-7) reg3=(n+8..15,k8-15)
                    mma_f16(acc[f][0], a[0], br[i2][t * 2], br[i2][t * 2 + 1]);
                    mma_f16(acc[f][1], a[1], br[i2][t * 2], br[i2][t * 2 + 1]);
                }
        }

        // ---- epilogue: write chunk's 64 columns as fp16 ----
        {
            const int n0c = ch * NTC;
            #pragma unroll
            for (int m = 0; m < 2; m++) {
                __half* r0p = g_projh + (m0 + warp * 32 + m * 16 + g) * OUTD + n0c + 2 * kq;
                __half* r1p = r0p + 8 * OUTD;
                #pragma unroll
                for (int f = 0; f < 8; f++) {
                    const int nOf = (f >> 1) * 16 + (f & 1) * 8;  // i2*16 + t*8
                    *(__half2*)(r0p + nOf) = __floats2half2_rn(acc[f][m][0], acc[f][m][1]);
                    *(__half2*)(r1p + nOf) = __floats2half2_rn(acc[f][m][2], acc[f][m][3]);
                }
            }
        }

        if (ch + 1 < NCH) CP_WAIT0();
        __syncthreads();
    }
}

// ---------------- Kernel 2: attention + aggregation + skip/mean ----------------
#define NTHREADS 192
extern __shared__ char asmem_raw[];

__global__ __launch_bounds__(NTHREADS, 5) void gat_attn_kernel(
    const float* __restrict__ A,      // (H, V, V)
    const float* __restrict__ ssrc,   // (1, H, COUT)
    const float* __restrict__ stgt,   // (1, H, COUT)
    float* __restrict__ out)          // (NROWS, COUT) flat
{
    __half* projh = (__half*)asmem_raw;                 // [V][OUTD] halves, 24192 B
    float*  fbase = (float*)(asmem_raw + ((V_ * OUTD * 2 + 15) & ~15));
    float* s1s  = fbase;              // [576]
    float* s2s  = s1s + OUTD;         // [576]
    float* ss_s = s2s + OUTD;         // [63]
    float* st_s = ss_s + 63;          // [63]
    float* w_s  = st_s + 63;          // [63][21]
    float* wsum = w_s + 63 * V_;      // [21][21]

    const int bp  = blockIdx.x;
    const int tid = threadIdx.x;

    // Phase 1: load proj tile + score vectors
    {
        const uint4* src = (const uint4*)(g_projh + (size_t)bp * V_ * OUTD);
        uint4* dst = (uint4*)projh;
        for (int i = tid; i < V_ * OUTD * 2 / 16; i += NTHREADS)
            dst[i] = src[i];
        for (int i = tid; i < OUTD / 4; i += NTHREADS) {
            ((float4*)s1s)[i] = ((const float4*)ssrc)[i];
            ((float4*)s2s)[i] = ((const float4*)stgt)[i];
        }
    }
    __syncthreads();

    // Phase 2: attention logits ss/st per (v,h)
    {
        const int wid  = tid >> 5;
        const int lane = tid & 31;
        for (int p = wid; p < 63; p += 6) {
            int v = p / 3, h = p % 3;
            const __half2* pr2 = (const __half2*)(projh + v * OUTD + h * COUT);
            const float* s1p = s1s + h * COUT;
            const float* s2p = s2s + h * COUT;
            float s1 = 0.f, s2 = 0.f;
            for (int c2 = lane; c2 < COUT / 2; c2 += 32) {
                float2 pv = __half22float2(pr2[c2]);
                s1 = fmaf(pv.x, s1p[2 * c2], fmaf(pv.y, s1p[2 * c2 + 1], s1));
                s2 = fmaf(pv.x, s2p[2 * c2], fmaf(pv.y, s2p[2 * c2 + 1], s2));
            }
            #pragma unroll
            for (int off = 16; off; off >>= 1) {
                s1 += __shfl_down_sync(0xffffffffu, s1, off);
                s2 += __shfl_down_sync(0xffffffffu, s2, off);
            }
            if (lane == 0) { ss_s[p] = s1; st_s[p] = s2; }
        }
    }
    __syncthreads();

    // Phase 3: masked softmax, one (h,i) row per thread
    if (tid < 63) {
        const int h = tid / 21;
        const int i = tid % 21;
        const float ssi = ss_s[i * 3 + h];
        const float* Arow = A + (h * V_ + i) * V_;
        float sc[21];
        float mx = -1e30f;
        #pragma unroll
        for (int j = 0; j < V_; j++) {
            float a = Arow[j];
            float s = ssi + st_s[j * 3 + h];
            s = (s >= 0.f) ? s : 0.2f * s;
            s += a;
            sc[j] = (a != 0.f) ? s : -1e30f;
            mx = fmaxf(mx, sc[j]);
        }
        float sum = 0.f;
        #pragma unroll
        for (int j = 0; j < V_; j++) {
            float e = (sc[j] > -1e29f) ? __expf(sc[j] - mx) : 0.f;
            sc[j] = e;
            sum += e;
        }
        float inv = 1.0f / sum;
        #pragma unroll
        for (int j = 0; j < V_; j++)
            w_s[tid * V_ + j] = sc[j] * inv;
    }
    __syncthreads();

    // Phase 3.5: pre-sum the 3 attention rows feeding each output row
    for (int idx = tid; idx < V_ * V_; idx += NTHREADS) {
        int r = idx / V_, j = idx % V_;
        int h = r / 7, q = r % 7;
        int i0 = h * 21 + 3 * q;
        wsum[idx] = w_s[(i0 + 0) * V_ + j]
                  + w_s[(i0 + 1) * V_ + j]
                  + w_s[(i0 + 2) * V_ + j];
    }
    __syncthreads();

    // Phase 4: aggregation + skip + mean (proj column packed as half2 regs)
    {
        const int c = tid;
        float* op = out + (size_t)bp * V_ * COUT;
        #pragma unroll
        for (int h = 0; h < H_; h++) {
            __half2 p2[11];   // 21 halves packed (last hi = 0)
            #pragma unroll
            for (int jp = 0; jp < 11; jp++) {
                __half lo = projh[(2 * jp) * OUTD + h * COUT + c];
                __half hi = (2 * jp + 1 < V_)
                          ? projh[(2 * jp + 1) * OUTD + h * COUT + c]
                          : __half(0.0f);
                p2[jp] = __halves2half2(lo, hi);
            }
            #pragma unroll
            for (int q = 0; q < 7; q++) {
                const int r = h * 7 + q;
                const float* ws = wsum + r * V_;
                float acc = __half2float(projh[r * OUTD + c])
                          + __half2float(projh[r * OUTD + COUT + c])
                          + __half2float(projh[r * OUTD + 2 * COUT + c]);
                #pragma unroll
                for (int jp = 0; jp < 11; jp++) {
                    float2 pv = __half22float2(p2[jp]);
                    acc = fmaf(ws[2 * jp], pv.x, acc);
                    if (2 * jp + 1 < V_)
                        acc = fmaf(ws[2 * jp + 1], pv.y, acc);
                }
                op[r * COUT + c] = acc * (1.0f / 3.0f);
            }
        }
    }
}

// ---------------- Launch ----------------
extern "C" void kernel_launch(void* const* d_in, const int* in_sizes, int n_in,
                              void* d_out, int out_size) {
    const float* x    = (const float*)d_in[0];
    const float* A    = (const float*)d_in[1];
    const float* W    = (const float*)d_in[2];
    const float* ssrc = (const float*)d_in[3];
    const float* stgt = (const float*)d_in[4];
    float* out = (float*)d_out;

    cudaFuncSetAttribute(gemm_kernel,
                         cudaFuncAttributeMaxDynamicSharedMemorySize, GEMM_SMEM);
    const int attn_smem = ((V_ * OUTD * 2 + 15) & ~15)
                        + (2 * OUTD + 63 + 63 + 63 * V_ + V_ * V_) * (int)sizeof(float);
    cudaFuncSetAttribute(gat_attn_kernel,
                         cudaFuncAttributeMaxDynamicSharedMemorySize, attn_smem);

    cvtX_kernel<<<dim3(PPB / 32, CIN / 32, B_), dim3(32, 8)>>>(x);
    cvtW_kernel<<<(OUTD * CIN + 255) / 256, 256>>>(W);
    gemm_kernel<<<NROWS / MT, 128, GEMM_SMEM>>>();
    gat_attn_kernel<<<B_ * T_, NTHREADS, attn_smem>>>(A, ssrc, stgt, out);
}

// round 12
// speedup vs baseline: 4.5188x; 1.0237x over previous
#include <cuda_runtime.h>
#include <cuda_fp16.h>
#include <cstdint>

// ---------------- Problem constants ----------------
#define B_    32
#define CIN   192
#define T_    256
#define V_    21
#define H_    3
#define COUT  192
#define OUTD  (H_*COUT)        // 576
#define NROWS (B_*T_*V_)       // 172032
#define PPB   (T_*V_)          // 5376

// ---------------- GEMM tiling ----------------
#define MT    128              // M tile (1344 blocks)
#define NTC   64               // N chunk (576 = 9*64)
#define NCH   9
#define AST   200              // A smem row stride (halves)
#define BST   200              // B smem row stride (halves)
#define SMEM_A_BYTES (MT*AST*2)          // 51200
#define SMEM_B_BYTES (NTC*BST*2)         // 25600
#define GEMM_SMEM (SMEM_A_BYTES + 2*SMEM_B_BYTES)  // 102400

// ---------------- Device scratch ----------------
__device__ __half g_projh[(size_t)NROWS * OUTD];  // 198 MB (fp16 intermediate)
__device__ __half g_Xh[(size_t)NROWS * CIN];      // 66 MB: x transposed+fp16
__device__ __half g_Wh[OUTD * CIN];               // W fp16

// ---------------- helpers ----------------
__device__ __forceinline__ uint32_t smem_u32(const void* p) {
    uint32_t a;
    asm("{ .reg .u64 t; cvta.to.shared.u64 t, %1; cvt.u32.u64 %0, t; }"
        : "=r"(a) : "l"(p));
    return a;
}
__device__ __forceinline__ void cp_async16(uint32_t dst, const void* src) {
    asm volatile("cp.async.cg.shared.global [%0], [%1], 16;"
                 :: "r"(dst), "l"(src) : "memory");
}
#define CP_COMMIT() asm volatile("cp.async.commit_group;" ::: "memory")
#define CP_WAIT0()  asm volatile("cp.async.wait_group 0;" ::: "memory")

__device__ __forceinline__ void ldmat_x4(uint32_t* r, uint32_t addr) {
    asm volatile("ldmatrix.sync.aligned.m8n8.x4.shared.b16 {%0,%1,%2,%3}, [%4];"
                 : "=r"(r[0]), "=r"(r[1]), "=r"(r[2]), "=r"(r[3]) : "r"(addr));
}
__device__ __forceinline__ void mma_f16(float* d, const uint32_t* a,
                                        uint32_t b0, uint32_t b1) {
    asm volatile(
        "mma.sync.aligned.m16n8k16.row.col.f32.f16.f16.f32 "
        "{%0,%1,%2,%3}, {%4,%5,%6,%7}, {%8,%9}, {%0,%1,%2,%3};"
        : "+f"(d[0]), "+f"(d[1]), "+f"(d[2]), "+f"(d[3])
        : "r"(a[0]), "r"(a[1]), "r"(a[2]), "r"(a[3]), "r"(b0), "r"(b1));
}

// ---------------- Kernel 0a: transpose+convert x -> g_Xh[(b,p)][c] fp16 ----------------
__global__ __launch_bounds__(256) void cvtX_kernel(const float* __restrict__ x) {
    __shared__ float tile[32][33];
    const int b  = blockIdx.z;
    const int c0 = blockIdx.y * 32;
    const int p0 = blockIdx.x * 32;
    const int tx = threadIdx.x;     // 32
    const int ty = threadIdx.y;     // 8
    const float* xb = x + (size_t)b * CIN * PPB;
    #pragma unroll
    for (int k = 0; k < 4; k++)
        tile[ty + k * 8][tx] = xb[(size_t)(c0 + ty + k * 8) * PPB + p0 + tx];
    __syncthreads();
    __half* xo = g_Xh + ((size_t)b * PPB + p0) * CIN + c0;
    #pragma unroll
    for (int k = 0; k < 4; k++)
        xo[(size_t)(ty + k * 8) * CIN + tx] = __float2half_rn(tile[tx][ty + k * 8]);
}

// ---------------- Kernel 0b: convert W -> fp16 ----------------
__global__ __launch_bounds__(256) void cvtW_kernel(const float* __restrict__ W) {
    int i = blockIdx.x * blockDim.x + threadIdx.x;
    if (i < OUTD * CIN) g_Wh[i] = __float2half_rn(W[i]);
}

// ---------------- Kernel 1: fp16 mma GEMM: projh = Xh @ Wh^T (fp32 accum) ----------------
__global__ __launch_bounds__(128, 2) void gemm_kernel() {
    extern __shared__ char smem[];
    const uint32_t sA = smem_u32(smem);
    const uint32_t sB = sA + SMEM_A_BYTES;

    const int tid  = threadIdx.x;
    const int warp = tid >> 5;
    const int lane = tid & 31;
    const int g    = lane >> 2;
    const int kq   = lane & 3;

    const size_t m0 = (size_t)blockIdx.x * MT;

    for (int i = tid; i < MT * 24; i += 128) {
        int r = i / 24, s = i % 24;
        cp_async16(sA + r * (AST * 2) + s * 16, g_Xh + (m0 + r) * CIN + s * 8);
    }
    for (int i = tid; i < NTC * 24; i += 128) {
        int r = i / 24, s = i % 24;
        cp_async16(sB + r * (BST * 2) + s * 16, g_Wh + (size_t)r * CIN + s * 8);
    }
    CP_COMMIT();
    CP_WAIT0();
    __syncthreads();

    const int aRow = warp * 32 + (lane & 15);
    const uint32_t aBase = sA + aRow * (AST * 2) + ((lane >> 4) * 8) * 2;
    const int bN   = (lane & 7) + ((lane >> 4) << 3);
    const uint32_t bKof = (((lane >> 3) & 1) * 8) * 2;

    for (int ch = 0; ch < NCH; ch++) {
        if (ch + 1 < NCH) {
            uint32_t dstb = sB + ((ch + 1) & 1) * SMEM_B_BYTES;
            const __half* src = g_Wh + (size_t)(ch + 1) * NTC * CIN;
            for (int i = tid; i < NTC * 24; i += 128) {
                int r = i / 24, s = i % 24;
                cp_async16(dstb + r * (BST * 2) + s * 16, src + (size_t)r * CIN + s * 8);
            }
            CP_COMMIT();
        }

        const uint32_t sBc = sB + (ch & 1) * SMEM_B_BYTES;
        uint32_t bBase[4];
        #pragma unroll
        for (int i2 = 0; i2 < 4; i2++)
            bBase[i2] = sBc + (i2 * 16 + bN) * (BST * 2) + bKof;

        float acc[8][2][4];
        #pragma unroll
        for (int f = 0; f < 8; f++)
            #pragma unroll
            for (int m = 0; m < 2; m++)
                #pragma unroll
                for (int q = 0; q < 4; q++) acc[f][m][q] = 0.0f;

        #pragma unroll 2
        for (int kk = 0; kk < 12; kk++) {
            const uint32_t kof = kk * 32;
            uint32_t a[2][4], br[4][4];
            ldmat_x4(a[0], aBase + kof);
            ldmat_x4(a[1], aBase + 16 * (AST * 2) + kof);
            #pragma unroll
            for (int i2 = 0; i2 < 4; i2++)
                ldmat_x4(br[i2], bBase[i2] + kof);
            #pragma unroll
            for (int i2 = 0; i2 < 4; i2++)
                #pragma unroll
                for (int t = 0; t < 2; t++) {
                    const int f = i2 * 2 + t;
                    mma_f16(acc[f][0], a[0], br[i2][t * 2], br[i2][t * 2 + 1]);
                    mma_f16(acc[f][1], a[1], br[i2][t * 2], br[i2][t * 2 + 1]);
                }
        }

        {
            const int n0c = ch * NTC;
            #pragma unroll
            for (int m = 0; m < 2; m++) {
                __half* r0p = g_projh + (m0 + warp * 32 + m * 16 + g) * OUTD + n0c + 2 * kq;
                __half* r1p = r0p + 8 * OUTD;
                #pragma unroll
                for (int f = 0; f < 8; f++) {
                    const int nOf = (f >> 1) * 16 + (f & 1) * 8;
                    *(__half2*)(r0p + nOf) = __floats2half2_rn(acc[f][m][0], acc[f][m][1]);
                    *(__half2*)(r1p + nOf) = __floats2half2_rn(acc[f][m][2], acc[f][m][3]);
                }
            }
        }

        if (ch + 1 < NCH) CP_WAIT0();
        __syncthreads();
    }
}

// ---------------- Kernel 2: attention + aggregation + skip/mean ----------------
#define NTHREADS 288
extern __shared__ char asmem_raw[];

__global__ __launch_bounds__(NTHREADS, 3) void gat_attn_kernel(
    const float* __restrict__ A,      // (H, V, V)
    const float* __restrict__ ssrc,   // (1, H, COUT)
    const float* __restrict__ stgt,   // (1, H, COUT)
    float* __restrict__ out)          // (NROWS, COUT) flat
{
    __half* projh = (__half*)asmem_raw;                 // [V][OUTD] halves, 24192 B
    float*  fbase = (float*)(asmem_raw + ((V_ * OUTD * 2 + 15) & ~15));
    float* s1s  = fbase;              // [576]
    float* s2s  = s1s + OUTD;         // [576]
    float* ss_s = s2s + OUTD;         // [63]
    float* st_s = ss_s + 63;          // [63]
    float* w_s  = st_s + 63;          // [63][21]
    float* wsum = w_s + 63 * V_;      // [21][21]

    const int bp  = blockIdx.x;
    const int tid = threadIdx.x;

    // Phase 1: load proj tile + score vectors
    {
        const uint4* src = (const uint4*)(g_projh + (size_t)bp * V_ * OUTD);
        uint4* dst = (uint4*)projh;
        for (int i = tid; i < V_ * OUTD * 2 / 16; i += NTHREADS)
            dst[i] = src[i];
        for (int i = tid; i < OUTD / 4; i += NTHREADS) {
            ((float4*)s1s)[i] = ((const float4*)ssrc)[i];
            ((float4*)s2s)[i] = ((const float4*)stgt)[i];
        }
    }
    __syncthreads();

    // Phase 2: attention logits ss/st per (v,h) — 63 units over 9 warps
    {
        const int wid  = tid >> 5;
        const int lane = tid & 31;
        for (int p = wid; p < 63; p += 9) {
            int v = p / 3, h = p % 3;
            const __half2* pr2 = (const __half2*)(projh + v * OUTD + h * COUT);
            const float* s1p = s1s + h * COUT;
            const float* s2p = s2s + h * COUT;
            float s1 = 0.f, s2 = 0.f;
            for (int c2 = lane; c2 < COUT / 2; c2 += 32) {
                float2 pv = __half22float2(pr2[c2]);
                s1 = fmaf(pv.x, s1p[2 * c2], fmaf(pv.y, s1p[2 * c2 + 1], s1));
                s2 = fmaf(pv.x, s2p[2 * c2], fmaf(pv.y, s2p[2 * c2 + 1], s2));
            }
            #pragma unroll
            for (int off = 16; off; off >>= 1) {
                s1 += __shfl_down_sync(0xffffffffu, s1, off);
                s2 += __shfl_down_sync(0xffffffffu, s2, off);
            }
            if (lane == 0) { ss_s[p] = s1; st_s[p] = s2; }
        }
    }
    __syncthreads();

    // Phase 3: masked softmax, one (h,i) row per thread
    if (tid < 63) {
        const int h = tid / 21;
        const int i = tid % 21;
        const float ssi = ss_s[i * 3 + h];
        const float* Arow = A + (h * V_ + i) * V_;
        float sc[21];
        float mx = -1e30f;
        #pragma unroll
        for (int j = 0; j < V_; j++) {
            float a = Arow[j];
            float s = ssi + st_s[j * 3 + h];
            s = (s >= 0.f) ? s : 0.2f * s;
            s += a;
            sc[j] = (a != 0.f) ? s : -1e30f;
            mx = fmaxf(mx, sc[j]);
        }
        float sum = 0.f;
        #pragma unroll
        for (int j = 0; j < V_; j++) {
            float e = (sc[j] > -1e29f) ? __expf(sc[j] - mx) : 0.f;
            sc[j] = e;
            sum += e;
        }
        float inv = 1.0f / sum;
        #pragma unroll
        for (int j = 0; j < V_; j++)
            w_s[tid * V_ + j] = sc[j] * inv;
    }
    __syncthreads();

    // Phase 3.5: pre-sum the 3 attention rows feeding each output row
    for (int idx = tid; idx < V_ * V_; idx += NTHREADS) {
        int r = idx / V_, j = idx % V_;
        int h = r / 7, q = r % 7;
        int i0 = h * 21 + 3 * q;
        wsum[idx] = w_s[(i0 + 0) * V_ + j]
                  + w_s[(i0 + 1) * V_ + j]
                  + w_s[(i0 + 2) * V_ + j];
    }
    __syncthreads();

    // Phase 4: aggregation + skip + mean — (h, column-pair) per thread
    {
        const int h  = tid / 96;        // 0..2
        const int c  = (tid % 96) * 2;  // even column
        float* op = out + (size_t)bp * V_ * COUT;

        __half2 p2[21];                  // this head's column-pair, all 21 rows
        #pragma unroll
        for (int j = 0; j < V_; j++)
            p2[j] = *(const __half2*)(projh + j * OUTD + h * COUT + c);

        #pragma unroll
        for (int q = 0; q < 7; q++) {
            const int r = h * 7 + q;
            const float* ws = wsum + r * V_;
            float2 k0 = __half22float2(*(const __half2*)(projh + r * OUTD + c));
            float2 k1 = __half22float2(*(const __half2*)(projh + r * OUTD + COUT + c));
            float2 k2 = __half22float2(*(const __half2*)(projh + r * OUTD + 2 * COUT + c));
            float ax = k0.x + k1.x + k2.x;
            float ay = k0.y + k1.y + k2.y;
            #pragma unroll
            for (int j = 0; j < V_; j++) {
                float wj = ws[j];
                float2 pv = __half22float2(p2[j]);
                ax = fmaf(wj, pv.x, ax);
                ay = fmaf(wj, pv.y, ay);
            }
            *(float2*)(op + r * COUT + c) = make_float2(ax * (1.0f / 3.0f),
                                                        ay * (1.0f / 3.0f));
        }
    }
}

// ---------------- Launch ----------------
extern "C" void kernel_launch(void* const* d_in, const int* in_sizes, int n_in,
                              void* d_out, int out_size) {
    const float* x    = (const float*)d_in[0];
    const float* A    = (const float*)d_in[1];
    const float* W    = (const float*)d_in[2];
    const float* ssrc = (const float*)d_in[3];
    const float* stgt = (const float*)d_in[4];
    float* out = (float*)d_out;

    cudaFuncSetAttribute(gemm_kernel,
                         cudaFuncAttributeMaxDynamicSharedMemorySize, GEMM_SMEM);
    const int attn_smem = ((V_ * OUTD * 2 + 15) & ~15)
                        + (2 * OUTD + 63 + 63 + 63 * V_ + V_ * V_) * (int)sizeof(float);
    cudaFuncSetAttribute(gat_attn_kernel,
                         cudaFuncAttributeMaxDynamicSharedMemorySize, attn_smem);

    cvtX_kernel<<<dim3(PPB / 32, CIN / 32, B_), dim3(32, 8)>>>(x);
    cvtW_kernel<<<(OUTD * CIN + 255) / 256, 256>>>(W);
    gemm_kernel<<<NROWS / MT, 128, GEMM_SMEM>>>();
    gat_attn_kernel<<<B_ * T_, NTHREADS, attn_smem>>>(A, ssrc, stgt, out);
}